// round 15
// baseline (speedup 1.0000x reference)
#include <cuda_runtime.h>
#include <cuda_fp16.h>
#include <math.h>
#include <stdint.h>

// ---------------- problem constants ----------------
#define B   512
#define D   256
#define C   100000
#define CPAD 100096              // padded to multiple of 128

#define S_SCALE   30.0f
#define COS_M     0.8775825618903728f
#define SIN_M     0.479425538604203f
#define THRESH   (-0.8775825618903728f)
#define MM_CONST  0.2397127693021015f
#define EPS_N     1e-12f

#define PRED_ELEMS   ((size_t)B * C)
#define W_ELEMS      ((size_t)C * D)

// ---------------- device scratch ----------------
__device__ float g_fnorm[B * D];
__device__ float g_tl[B];
__device__ float g_ctm[B];
__device__ float g_ftl[B];
__device__ float g_tnew;
__device__ int   g_counts[C];        // invariant: all-zero at entry (restored by cleanup)
__device__ int   g_slotmap[C];       // invariant: all-zero at entry (restored by cleanup)
__device__ float g_scratch2[B * D];  // invariant: all-zero at entry (restored by cleanup)
__device__ int   g_targets[B];

// A fragment-packed: [mblk(32)][chunk(4)][kk(4)][lane(32)] x uint4 (fp16 f)
__device__ uint4 g_Afrag[32 * 4 * 4 * 32];
// B fragment-packed: [nblk(CPAD/8)][chunk(4)][q(2)][lane(32)] x uint4 (fp16 W)
__device__ uint4 g_Bfrag[(size_t)(CPAD / 8) * 4 * 2 * 32];

// ---------------- PTX helpers ----------------
__device__ __forceinline__ void mma16816(float* d, const uint32_t* a, const uint32_t* b) {
    asm volatile(
        "mma.sync.aligned.m16n8k16.row.col.f32.f16.f16.f32 "
        "{%0,%1,%2,%3}, {%4,%5,%6,%7}, {%8,%9}, {%0,%1,%2,%3};"
        : "+f"(d[0]), "+f"(d[1]), "+f"(d[2]), "+f"(d[3])
        : "r"(a[0]), "r"(a[1]), "r"(a[2]), "r"(a[3]), "r"(b[0]), "r"(b[1]));
}

// ---------------- small helper ----------------
__device__ __forceinline__ float block_reduce_sum(float v) {
    __shared__ float s[32];
    int lane = threadIdx.x & 31;
    int w    = threadIdx.x >> 5;
    #pragma unroll
    for (int o = 16; o; o >>= 1) v += __shfl_down_sync(0xffffffffu, v, o);
    __syncthreads();
    if (lane == 0) s[w] = v;
    __syncthreads();
    int nw = blockDim.x >> 5;
    v = (threadIdx.x < nw) ? s[threadIdx.x] : 0.0f;
    if (w == 0) {
        #pragma unroll
        for (int o = 16; o; o >>= 1) v += __shfl_down_sync(0xffffffffu, v, o);
        if (lane == 0) s[0] = v;
    }
    __syncthreads();
    return s[0];
}

// ---------------- kernel 1: normalize + targets + target logit + segment-sum --------
__global__ void k_norm_accum(const float* __restrict__ features,
                             const float* __restrict__ weight,
                             const int* __restrict__ traw) {
    __shared__ int oddnz;
    __shared__ int slot_s;
    int b = blockIdx.x;
    int d = threadIdx.x;
    if (d == 0) oddnz = 0;
    __syncthreads();
    if (d < B / 2) {
        if (traw[2 * d + 1] != 0) atomicOr(&oddnz, 1);
    }
    __syncthreads();
    int tgt = (oddnz == 0) ? traw[2 * b] : traw[b];
    if (d == 0) {
        g_targets[b] = tgt;
        int prev = atomicCAS(&g_slotmap[tgt], 0, b + 1);
        slot_s = prev ? (prev - 1) : b;
        atomicAdd(&g_counts[tgt], 1);
    }

    float v = features[b * D + d];
    float ss = block_reduce_sum(v * v);
    float inv = 1.0f / fmaxf(sqrtf(ss), EPS_N);
    float f = v * inv;
    g_fnorm[b * D + d] = f;

    atomicAdd(&g_scratch2[slot_s * D + d], f);

    float p = f * weight[(size_t)tgt * D + d];
    float dot = block_reduce_sum(p);
    if (d == 0) g_tl[b] = dot;
}

// ---------------- kernel 2: pack A fragments + (block 64) row params ----------------
__global__ void __launch_bounds__(256)
k_pack_A_row(const float* __restrict__ t_in, float* __restrict__ out_t) {
    if (blockIdx.x == 64) {
        int t = threadIdx.x;                      // 0..255, two rows each
        float tl0 = g_tl[t];
        float tl1 = g_tl[t + 256];
        float s = block_reduce_sum(tl0 + tl1);
        if (t == 0) {
            float tn = s * (1.0f / (float)B) * 0.01f + 0.99f * t_in[0];
            g_tnew = tn;
            out_t[0] = tn;
        }
        #pragma unroll
        for (int h = 0; h < 2; ++h) {
            int bb = t + h * 256;
            float tl = h ? tl1 : tl0;
            float sn = sqrtf(fmaxf(1.0f - tl * tl, 0.0f));
            float ctm = tl * COS_M - sn * SIN_M;
            g_ctm[bb] = ctm;
            g_ftl[bb] = (tl > THRESH) ? ctm : (tl - MM_CONST);
        }
        return;
    }

    int tid = blockIdx.x * 256 + threadIdx.x;     // 0..16383
    int lane16 = tid & 31;
    int g    = lane16 >> 2;
    int tig  = lane16 & 3;
    int kk   = (tid >> 5) & 3;
    int chunk = (tid >> 7) & 3;
    int mblk = tid >> 9;
    int k0 = chunk * 64 + kk * 16;
    int m  = mblk * 16 + g;
    int c0 = k0 + tig * 2;
    int c1 = c0 + 8;

    float f[8];
    f[0] = g_fnorm[m * D + c0];       f[1] = g_fnorm[m * D + c0 + 1];
    f[2] = g_fnorm[(m + 8) * D + c0]; f[3] = g_fnorm[(m + 8) * D + c0 + 1];
    f[4] = g_fnorm[m * D + c1];       f[5] = g_fnorm[m * D + c1 + 1];
    f[6] = g_fnorm[(m + 8) * D + c1]; f[7] = g_fnorm[(m + 8) * D + c1 + 1];

    uint4 out;
    __half2 p0 = __floats2half2_rn(f[0], f[1]); out.x = *(uint32_t*)&p0;
    __half2 p1 = __floats2half2_rn(f[2], f[3]); out.y = *(uint32_t*)&p1;
    __half2 p2 = __floats2half2_rn(f[4], f[5]); out.z = *(uint32_t*)&p2;
    __half2 p3 = __floats2half2_rn(f[6], f[7]); out.w = *(uint32_t*)&p3;
    g_Afrag[tid] = out;
}

// ---------------- kernel 3: fp16(W) B-fragment pack (warp per class) ----------------
__global__ void __launch_bounds__(256)
k_pack_B(const float* __restrict__ weight) {
    int w    = threadIdx.x >> 5;
    int lane = threadIdx.x & 31;
    int c    = blockIdx.x * 8 + w;
    int nblk = c >> 3;
    int g    = c & 7;

    float wv[8];
    if (c < C) {
        size_t idx = (size_t)c * D + lane * 8;
        float4 w0 = *(const float4*)&weight[idx];
        float4 w1 = *(const float4*)&weight[idx + 4];
        wv[0] = w0.x; wv[1] = w0.y; wv[2] = w0.z; wv[3] = w0.w;
        wv[4] = w1.x; wv[5] = w1.y; wv[6] = w1.z; wv[7] = w1.w;
    } else {
        #pragma unroll
        for (int i = 0; i < 8; ++i) wv[i] = 0.0f;
    }

    uint32_t* Bf32 = (uint32_t*)g_Bfrag;
    #pragma unroll
    for (int jj = 0; jj < 4; ++jj) {
        int k     = lane * 8 + jj * 2;
        int chunk = k >> 6;
        int ck    = k & 63;
        int kk    = ck >> 4;
        int q     = kk >> 1;
        int ii    = kk & 1;
        int h     = (ck >> 3) & 1;
        int tg    = (ck & 7) >> 1;
        size_t off32 = (((size_t)nblk * 4 + chunk) * 2 + q) * 128
                     + g * 16 + tg * 4 + ii * 2 + h;
        __half2 hp = __floats2half2_rn(wv[2 * jj], wv[2 * jj + 1]);
        Bf32[off32] = *(uint32_t*)&hp;
    }
}

// ---------------- kernel 4 (fat): GEMM + ArcFace epilogue | EMA weight update -------
// grid (5, 782): blockIdx.x < 4  -> GEMM CTA 128(m) x 128(n), 16 warps, 32x32 tiles
//                blockIdx.x == 4 -> EMA update block for classes [y*128, y*128+128)
__global__ void __launch_bounds__(512, 1)
k_gemm_ema(float* __restrict__ pred,
           const float* __restrict__ weight,
           float* __restrict__ newW) {
    const int tid  = threadIdx.x;
    const int wid  = tid >> 5;
    const int lane = tid & 31;

    if (blockIdx.x == 4) {
        // ---- EMA weight-update block: 16 warps x 8 classes = 128 classes ----
        const int cbase = blockIdx.y * 128 + wid * 8;
        #pragma unroll 2
        for (int i = 0; i < 8; ++i) {
            int c = cbase + i;
            if (c >= C) break;
            size_t idx = (size_t)c * D + lane * 8;
            float4 w0 = *(const float4*)&weight[idx];
            float4 w1 = *(const float4*)&weight[idx + 4];
            int sm = g_slotmap[c];
            if (sm != 0) {
                int cnt = g_counts[c];
                const float* srow = &g_scratch2[(sm - 1) * D + lane * 8];
                float4 s0 = *(const float4*)srow;
                float4 s1 = *(const float4*)(srow + 4);
                float wv[8] = {w0.x, w0.y, w0.z, w0.w, w1.x, w1.y, w1.z, w1.w};
                float sv[8] = {s0.x, s0.y, s0.z, s0.w, s1.x, s1.y, s1.z, s1.w};
                float inv_cnt = 1.0f / (float)cnt;
                float u[8], ss = 0.0f;
                #pragma unroll
                for (int e = 0; e < 8; ++e) {
                    u[e] = 0.5f * wv[e] + 0.5f * (sv[e] * inv_cnt);
                    ss += u[e] * u[e];
                }
                #pragma unroll
                for (int o = 16; o; o >>= 1) ss += __shfl_xor_sync(0xffffffffu, ss, o);
                float inv = 1.0f / fmaxf(sqrtf(ss), EPS_N);
                *(float4*)&newW[idx]     = make_float4(u[0]*inv, u[1]*inv, u[2]*inv, u[3]*inv);
                *(float4*)&newW[idx + 4] = make_float4(u[4]*inv, u[5]*inv, u[6]*inv, u[7]*inv);
            } else {
                *(float4*)&newW[idx]     = w0;
                *(float4*)&newW[idx + 4] = w1;
            }
        }
        return;
    }

    // ---- GEMM CTA (byte-identical to the R13 113.4us config) ----
    const int wm   = wid >> 2;          // 0..3
    const int wn   = wid & 3;           // 0..3
    const int g    = lane >> 2;         // 0..7
    const int tig  = lane & 3;          // 0..3
    const int m0   = blockIdx.x * 128;  // m fastest -> B L2 reuse
    const int n0   = blockIdx.y * 128;

    const int mblk0 = (m0 >> 4) + wm * 2;       // 2 m-blocks of 16 rows
    const int nblk0 = (n0 >> 3) + wn * 4;       // 4 n-blocks of 8 rows

    float acc[2][4][4];
    #pragma unroll
    for (int i = 0; i < 2; ++i)
        #pragma unroll
        for (int j = 0; j < 4; ++j)
            #pragma unroll
            for (int r = 0; r < 4; ++r) acc[i][j][r] = 0.0f;

    // B-fragment double buffer: prefetch (j=0, q=0)
    uint4 bvA[4], bvB[4];
    #pragma unroll
    for (int nj = 0; nj < 4; ++nj)
        bvA[nj] = g_Bfrag[(((size_t)(nblk0 + nj) * 4 + 0) * 2 + 0) * 32 + lane];

    for (int j = 0; j < 4; ++j) {               // K chunks of 64 (rolled)
        const int jn = (j + 1) & 3;
        #pragma unroll
        for (int nj = 0; nj < 4; ++nj)
            bvB[nj] = g_Bfrag[(((size_t)(nblk0 + nj) * 4 + j) * 2 + 1) * 32 + lane];
        #pragma unroll
        for (int i = 0; i < 2; ++i) {
            uint4 av[2];
            #pragma unroll
            for (int mi = 0; mi < 2; ++mi)
                av[mi] = g_Afrag[(((mblk0 + mi) * 4 + j) * 4 + i) * 32 + lane];
            #pragma unroll
            for (int mi = 0; mi < 2; ++mi) {
                #pragma unroll
                for (int nj = 0; nj < 4; ++nj) {
                    uint32_t bb[2];
                    bb[0] = i ? bvA[nj].z : bvA[nj].x;
                    bb[1] = i ? bvA[nj].w : bvA[nj].y;
                    mma16816(acc[mi][nj], (const uint32_t*)&av[mi], bb);
                }
            }
        }
        #pragma unroll
        for (int nj = 0; nj < 4; ++nj)
            bvA[nj] = g_Bfrag[(((size_t)(nblk0 + nj) * 4 + jn) * 2 + 0) * 32 + lane];
        #pragma unroll
        for (int i = 0; i < 2; ++i) {
            uint4 av[2];
            #pragma unroll
            for (int mi = 0; mi < 2; ++mi)
                av[mi] = g_Afrag[(((mblk0 + mi) * 4 + j) * 4 + 2 + i) * 32 + lane];
            #pragma unroll
            for (int mi = 0; mi < 2; ++mi) {
                #pragma unroll
                for (int nj = 0; nj < 4; ++nj) {
                    uint32_t bb[2];
                    bb[0] = i ? bvB[nj].z : bvB[nj].x;
                    bb[1] = i ? bvB[nj].w : bvB[nj].y;
                    mma16816(acc[mi][nj], (const uint32_t*)&av[mi], bb);
                }
            }
        }
    }

    // ---- fused ArcFace epilogue ----
    const float tn = g_tnew;
    #pragma unroll
    for (int mi = 0; mi < 2; ++mi) {
        int r0 = m0 + wm * 32 + mi * 16 + g;
        #pragma unroll
        for (int half = 0; half < 2; ++half) {
            int brow = r0 + half * 8;
            int tgt   = g_targets[brow];
            float ctm = g_ctm[brow];
            float ftl = g_ftl[brow];
            size_t rowbase = (size_t)brow * C;
            #pragma unroll
            for (int nj = 0; nj < 4; ++nj) {
                int c = n0 + wn * 32 + nj * 8 + tig * 2;
                float v0 = acc[mi][nj][half * 2 + 0];
                float v1 = acc[mi][nj][half * 2 + 1];
                v0 = (v0 > ctm) ? v0 * (tn + v0) : v0;
                v1 = (v1 > ctm) ? v1 * (tn + v1) : v1;
                if (c == tgt)     v0 = ftl;
                if (c + 1 == tgt) v1 = ftl;
                v0 *= S_SCALE;
                v1 *= S_SCALE;
                if (c + 1 < C) {
                    *(float2*)&pred[rowbase + c] = make_float2(v0, v1);
                } else if (c < C) {
                    pred[rowbase + c] = v0;
                }
            }
        }
    }
}

// ---------------- kernel 5: restore zero invariants ----------------
__global__ void k_cleanup() {
    int b = blockIdx.x;
    int d = threadIdx.x;
    g_scratch2[b * D + d] = 0.0f;
    if (d == 0) {
        int tgt = g_targets[b];
        g_slotmap[tgt] = 0;
        g_counts[tgt]  = 0;
    }
}

// ---------------- launch ----------------
extern "C" void kernel_launch(void* const* d_in, const int* in_sizes, int n_in,
                              void* d_out, int out_size) {
    const float* features = (const float*)d_in[0];
    const int*   traw     = (const int*)d_in[1];
    const float* weight   = (const float*)d_in[2];
    const float* t_in     = (const float*)d_in[3];

    float* out    = (float*)d_out;
    float* pred   = out;                        // [B, C]
    float* newW   = out + PRED_ELEMS;           // [C, D]
    float* out_t  = out + PRED_ELEMS + W_ELEMS; // [1]

    k_norm_accum<<<B, D>>>(features, weight, traw);     // 1
    k_pack_A_row<<<65, 256>>>(t_in, out_t);             // 2
    k_pack_B<<<CPAD / 8, 256>>>(weight);                // 3
    dim3 grid(5, CPAD / 128);                           // x<4: GEMM, x==4: EMA
    k_gemm_ema<<<grid, 512>>>(pred, weight, newW);      // 4  <- profiled slot
    k_cleanup<<<B, D>>>();                              // 5
}

// round 16
// speedup vs baseline: 1.1315x; 1.1315x over previous
#include <cuda_runtime.h>
#include <cuda_fp16.h>
#include <math.h>
#include <stdint.h>

// ---------------- problem constants ----------------
#define B   512
#define D   256
#define C   100000
#define CPAD 100096              // padded to multiple of 128

#define S_SCALE   30.0f
#define COS_M     0.8775825618903728f
#define SIN_M     0.479425538604203f
#define THRESH   (-0.8775825618903728f)
#define MM_CONST  0.2397127693021015f
#define EPS_N     1e-12f

#define PRED_ELEMS   ((size_t)B * C)
#define W_ELEMS      ((size_t)C * D)

// ---------------- device scratch ----------------
__device__ float g_fnorm[B * D];
__device__ float g_tl[B];
__device__ float g_ctm[B];
__device__ float g_ftl[B];
__device__ float g_tnew;
__device__ int   g_counts[C];        // invariant: all-zero at entry (restored by WU)
__device__ int   g_slotmap[C];       // invariant: all-zero at entry (restored by WU)
__device__ float g_scratch2[B * D];  // invariant: all-zero at entry (restored by WU)
__device__ int   g_targets[B];

// A fragment-packed: [mblk(32)][chunk(4)][kk(4)][lane(32)] x uint4 (fp16 f)
__device__ uint4 g_Afrag[32 * 4 * 4 * 32];
// B fragment-packed: [nblk(CPAD/8)][chunk(4)][q(2)][lane(32)] x uint4 (fp16 W)
__device__ uint4 g_Bfrag[(size_t)(CPAD / 8) * 4 * 2 * 32];

// ---------------- PTX helpers ----------------
__device__ __forceinline__ void mma16816(float* d, const uint32_t* a, const uint32_t* b) {
    asm volatile(
        "mma.sync.aligned.m16n8k16.row.col.f32.f16.f16.f32 "
        "{%0,%1,%2,%3}, {%4,%5,%6,%7}, {%8,%9}, {%0,%1,%2,%3};"
        : "+f"(d[0]), "+f"(d[1]), "+f"(d[2]), "+f"(d[3])
        : "r"(a[0]), "r"(a[1]), "r"(a[2]), "r"(a[3]), "r"(b[0]), "r"(b[1]));
}

// ---------------- small helper ----------------
__device__ __forceinline__ float block_reduce_sum(float v) {
    __shared__ float s[32];
    int lane = threadIdx.x & 31;
    int w    = threadIdx.x >> 5;
    #pragma unroll
    for (int o = 16; o; o >>= 1) v += __shfl_down_sync(0xffffffffu, v, o);
    __syncthreads();
    if (lane == 0) s[w] = v;
    __syncthreads();
    int nw = blockDim.x >> 5;
    v = (threadIdx.x < nw) ? s[threadIdx.x] : 0.0f;
    if (w == 0) {
        #pragma unroll
        for (int o = 16; o; o >>= 1) v += __shfl_down_sync(0xffffffffu, v, o);
        if (lane == 0) s[0] = v;
    }
    __syncthreads();
    return s[0];
}

// ---------------- kernel 1: normalize + targets + target logit + segment-sum --------
__global__ void k_norm_accum(const float* __restrict__ features,
                             const float* __restrict__ weight,
                             const int* __restrict__ traw) {
    __shared__ int oddnz;
    __shared__ int slot_s;
    int b = blockIdx.x;
    int d = threadIdx.x;
    if (d == 0) oddnz = 0;
    __syncthreads();
    if (d < B / 2) {
        if (traw[2 * d + 1] != 0) atomicOr(&oddnz, 1);
    }
    __syncthreads();
    int tgt = (oddnz == 0) ? traw[2 * b] : traw[b];
    if (d == 0) {
        g_targets[b] = tgt;
        int prev = atomicCAS(&g_slotmap[tgt], 0, b + 1);
        slot_s = prev ? (prev - 1) : b;
        atomicAdd(&g_counts[tgt], 1);
    }

    float v = features[b * D + d];
    float ss = block_reduce_sum(v * v);
    float inv = 1.0f / fmaxf(sqrtf(ss), EPS_N);
    float f = v * inv;
    g_fnorm[b * D + d] = f;

    atomicAdd(&g_scratch2[slot_s * D + d], f);

    float p = f * weight[(size_t)tgt * D + d];
    float dot = block_reduce_sum(p);
    if (d == 0) g_tl[b] = dot;
}

// ---------------- kernel 2: pack A fragments + (block 64) row params ----------------
__global__ void __launch_bounds__(256)
k_pack_A_row(const float* __restrict__ t_in, float* __restrict__ out_t) {
    if (blockIdx.x == 64) {
        int t = threadIdx.x;                      // 0..255, two rows each
        float tl0 = g_tl[t];
        float tl1 = g_tl[t + 256];
        float s = block_reduce_sum(tl0 + tl1);
        if (t == 0) {
            float tn = s * (1.0f / (float)B) * 0.01f + 0.99f * t_in[0];
            g_tnew = tn;
            out_t[0] = tn;
        }
        #pragma unroll
        for (int h = 0; h < 2; ++h) {
            int bb = t + h * 256;
            float tl = h ? tl1 : tl0;
            float sn = sqrtf(fmaxf(1.0f - tl * tl, 0.0f));
            float ctm = tl * COS_M - sn * SIN_M;
            g_ctm[bb] = ctm;
            g_ftl[bb] = (tl > THRESH) ? ctm : (tl - MM_CONST);
        }
        return;
    }

    int tid = blockIdx.x * 256 + threadIdx.x;     // 0..16383
    int lane16 = tid & 31;
    int g    = lane16 >> 2;
    int tig  = lane16 & 3;
    int kk   = (tid >> 5) & 3;
    int chunk = (tid >> 7) & 3;
    int mblk = tid >> 9;
    int k0 = chunk * 64 + kk * 16;
    int m  = mblk * 16 + g;
    int c0 = k0 + tig * 2;
    int c1 = c0 + 8;

    float f[8];
    f[0] = g_fnorm[m * D + c0];       f[1] = g_fnorm[m * D + c0 + 1];
    f[2] = g_fnorm[(m + 8) * D + c0]; f[3] = g_fnorm[(m + 8) * D + c0 + 1];
    f[4] = g_fnorm[m * D + c1];       f[5] = g_fnorm[m * D + c1 + 1];
    f[6] = g_fnorm[(m + 8) * D + c1]; f[7] = g_fnorm[(m + 8) * D + c1 + 1];

    uint4 out;
    __half2 p0 = __floats2half2_rn(f[0], f[1]); out.x = *(uint32_t*)&p0;
    __half2 p1 = __floats2half2_rn(f[2], f[3]); out.y = *(uint32_t*)&p1;
    __half2 p2 = __floats2half2_rn(f[4], f[5]); out.z = *(uint32_t*)&p2;
    __half2 p3 = __floats2half2_rn(f[6], f[7]); out.w = *(uint32_t*)&p3;
    g_Afrag[tid] = out;
}

// ---------------- kernel 3: weight update + fp16(W) B-fragment pack + cleanup -------
// warp per class; after consuming slotmap/counts/scratch2, restores their zeros.
__global__ void __launch_bounds__(256)
k_weight_update(const float* __restrict__ weight,
                float* __restrict__ newW) {
    int w    = threadIdx.x >> 5;
    int lane = threadIdx.x & 31;
    int c    = blockIdx.x * 8 + w;
    int nblk = c >> 3;
    int g    = c & 7;

    float wv[8];
    if (c < C) {
        size_t idx = (size_t)c * D + lane * 8;
        float4 w0 = *(const float4*)&weight[idx];
        float4 w1 = *(const float4*)&weight[idx + 4];
        wv[0] = w0.x; wv[1] = w0.y; wv[2] = w0.z; wv[3] = w0.w;
        wv[4] = w1.x; wv[5] = w1.y; wv[6] = w1.z; wv[7] = w1.w;
    } else {
        #pragma unroll
        for (int i = 0; i < 8; ++i) wv[i] = 0.0f;
    }

    // fragment-packed fp16 store of OLD weight
    uint32_t* Bf32 = (uint32_t*)g_Bfrag;
    #pragma unroll
    for (int jj = 0; jj < 4; ++jj) {
        int k     = lane * 8 + jj * 2;
        int chunk = k >> 6;
        int ck    = k & 63;
        int kk    = ck >> 4;
        int q     = kk >> 1;
        int ii    = kk & 1;
        int h     = (ck >> 3) & 1;
        int tg    = (ck & 7) >> 1;
        size_t off32 = (((size_t)nblk * 4 + chunk) * 2 + q) * 128
                     + g * 16 + tg * 4 + ii * 2 + h;
        __half2 hp = __floats2half2_rn(wv[2 * jj], wv[2 * jj + 1]);
        Bf32[off32] = *(uint32_t*)&hp;
    }

    if (c >= C) return;

    size_t idx = (size_t)c * D + lane * 8;
    int sm = g_slotmap[c];
    if (sm != 0) {
        int cnt = g_counts[c];
        float* srow = &g_scratch2[(sm - 1) * D + lane * 8];
        float4 s0 = *(const float4*)srow;
        float4 s1 = *(const float4*)(srow + 4);
        float sv[8] = {s0.x, s0.y, s0.z, s0.w, s1.x, s1.y, s1.z, s1.w};
        float inv_cnt = 1.0f / (float)cnt;
        float u[8], ss = 0.0f;
        #pragma unroll
        for (int i = 0; i < 8; ++i) {
            u[i] = 0.5f * wv[i] + 0.5f * (sv[i] * inv_cnt);
            ss += u[i] * u[i];
        }
        #pragma unroll
        for (int o = 16; o; o >>= 1) ss += __shfl_xor_sync(0xffffffffu, ss, o);
        float inv = 1.0f / fmaxf(sqrtf(ss), EPS_N);
        *(float4*)&newW[idx]     = make_float4(u[0] * inv, u[1] * inv, u[2] * inv, u[3] * inv);
        *(float4*)&newW[idx + 4] = make_float4(u[4] * inv, u[5] * inv, u[6] * inv, u[7] * inv);
        // ---- restore zero invariants (this warp is the last reader) ----
        *(float4*)srow       = make_float4(0.f, 0.f, 0.f, 0.f);
        *(float4*)(srow + 4) = make_float4(0.f, 0.f, 0.f, 0.f);
        if (lane == 0) {
            g_slotmap[c] = 0;
            g_counts[c]  = 0;
        }
    } else {
        *(float4*)&newW[idx]     = make_float4(wv[0], wv[1], wv[2], wv[3]);
        *(float4*)&newW[idx + 4] = make_float4(wv[4], wv[5], wv[6], wv[7]);
    }
}

// ---------------- kernel 4: smem-free mma.sync GEMM + ArcFace epilogue ----------------
// CTA 128(m) x 128(n), 16 warps in 4(m) x 4(n); warp tile 32x32; K = 256.
// Byte-identical to the measured 113.4us configuration.
__global__ void __launch_bounds__(512, 1)
k_gemm_mma(float* __restrict__ pred) {
    const int tid  = threadIdx.x;
    const int wid  = tid >> 5;
    const int lane = tid & 31;
    const int wm   = wid >> 2;          // 0..3
    const int wn   = wid & 3;           // 0..3
    const int g    = lane >> 2;         // 0..7
    const int tig  = lane & 3;          // 0..3
    const int m0   = blockIdx.x * 128;  // m fastest -> B L2 reuse
    const int n0   = blockIdx.y * 128;

    const int mblk0 = (m0 >> 4) + wm * 2;       // 2 m-blocks of 16 rows
    const int nblk0 = (n0 >> 3) + wn * 4;       // 4 n-blocks of 8 rows

    float acc[2][4][4];
    #pragma unroll
    for (int i = 0; i < 2; ++i)
        #pragma unroll
        for (int j = 0; j < 4; ++j)
            #pragma unroll
            for (int r = 0; r < 4; ++r) acc[i][j][r] = 0.0f;

    // B-fragment double buffer: prefetch (j=0, q=0)
    uint4 bvA[4], bvB[4];
    #pragma unroll
    for (int nj = 0; nj < 4; ++nj)
        bvA[nj] = g_Bfrag[(((size_t)(nblk0 + nj) * 4 + 0) * 2 + 0) * 32 + lane];

    for (int j = 0; j < 4; ++j) {               // K chunks of 64 (rolled)
        const int jn = (j + 1) & 3;
        #pragma unroll
        for (int nj = 0; nj < 4; ++nj)
            bvB[nj] = g_Bfrag[(((size_t)(nblk0 + nj) * 4 + j) * 2 + 1) * 32 + lane];
        #pragma unroll
        for (int i = 0; i < 2; ++i) {
            uint4 av[2];
            #pragma unroll
            for (int mi = 0; mi < 2; ++mi)
                av[mi] = g_Afrag[(((mblk0 + mi) * 4 + j) * 4 + i) * 32 + lane];
            #pragma unroll
            for (int mi = 0; mi < 2; ++mi) {
                #pragma unroll
                for (int nj = 0; nj < 4; ++nj) {
                    uint32_t bb[2];
                    bb[0] = i ? bvA[nj].z : bvA[nj].x;
                    bb[1] = i ? bvA[nj].w : bvA[nj].y;
                    mma16816(acc[mi][nj], (const uint32_t*)&av[mi], bb);
                }
            }
        }
        #pragma unroll
        for (int nj = 0; nj < 4; ++nj)
            bvA[nj] = g_Bfrag[(((size_t)(nblk0 + nj) * 4 + jn) * 2 + 0) * 32 + lane];
        #pragma unroll
        for (int i = 0; i < 2; ++i) {
            uint4 av[2];
            #pragma unroll
            for (int mi = 0; mi < 2; ++mi)
                av[mi] = g_Afrag[(((mblk0 + mi) * 4 + j) * 4 + 2 + i) * 32 + lane];
            #pragma unroll
            for (int mi = 0; mi < 2; ++mi) {
                #pragma unroll
                for (int nj = 0; nj < 4; ++nj) {
                    uint32_t bb[2];
                    bb[0] = i ? bvB[nj].z : bvB[nj].x;
                    bb[1] = i ? bvB[nj].w : bvB[nj].y;
                    mma16816(acc[mi][nj], (const uint32_t*)&av[mi], bb);
                }
            }
        }
    }

    // ---- fused ArcFace epilogue ----
    const float tn = g_tnew;
    #pragma unroll
    for (int mi = 0; mi < 2; ++mi) {
        int r0 = m0 + wm * 32 + mi * 16 + g;
        #pragma unroll
        for (int half = 0; half < 2; ++half) {
            int brow = r0 + half * 8;
            int tgt   = g_targets[brow];
            float ctm = g_ctm[brow];
            float ftl = g_ftl[brow];
            size_t rowbase = (size_t)brow * C;
            #pragma unroll
            for (int nj = 0; nj < 4; ++nj) {
                int c = n0 + wn * 32 + nj * 8 + tig * 2;
                float v0 = acc[mi][nj][half * 2 + 0];
                float v1 = acc[mi][nj][half * 2 + 1];
                v0 = (v0 > ctm) ? v0 * (tn + v0) : v0;
                v1 = (v1 > ctm) ? v1 * (tn + v1) : v1;
                if (c == tgt)     v0 = ftl;
                if (c + 1 == tgt) v1 = ftl;
                v0 *= S_SCALE;
                v1 *= S_SCALE;
                if (c + 1 < C) {
                    *(float2*)&pred[rowbase + c] = make_float2(v0, v1);
                } else if (c < C) {
                    pred[rowbase + c] = v0;
                }
            }
        }
    }
}

// ---------------- launch ----------------
extern "C" void kernel_launch(void* const* d_in, const int* in_sizes, int n_in,
                              void* d_out, int out_size) {
    const float* features = (const float*)d_in[0];
    const int*   traw     = (const int*)d_in[1];
    const float* weight   = (const float*)d_in[2];
    const float* t_in     = (const float*)d_in[3];

    float* out    = (float*)d_out;
    float* pred   = out;                        // [B, C]
    float* newW   = out + PRED_ELEMS;           // [C, D]
    float* out_t  = out + PRED_ELEMS + W_ELEMS; // [1]

    k_norm_accum<<<B, D>>>(features, weight, traw);     // 1
    k_pack_A_row<<<65, 256>>>(t_in, out_t);             // 2
    k_weight_update<<<CPAD / 8, 256>>>(weight, newW);   // 3 (incl. invariant restore)
    dim3 grid(B / 128, CPAD / 128);                     // (4, 782), m fastest
    k_gemm_mma<<<grid, 512>>>(pred);                    // 4  <- profiled slot
}